// round 14
// baseline (speedup 1.0000x reference)
#include <cuda_runtime.h>
#include <cuda_bf16.h>
#include <mma.h>
#include <cstdint>

using namespace nvcuda;

#define Bb 8
#define Ss 2048
#define Dd 1024
#define Mtot (Bb * Ss)
#define NSPLIT 8
#define MTKS 4

#define NT_Y   512                    // y tiles (128 rowblocks x 4 n-blocks)
#define NT_ALL (NT_Y + 1024)          // + flash tiles (128 rowblocks x 8 splits)

// ---------------------------------------------------------------------------
// Device-global scratch
// ---------------------------------------------------------------------------
__device__ __nv_bfloat16 g_xhi[(size_t)Mtot * Dd];
__device__ __nv_bfloat16 g_xlo[(size_t)Mtot * Dd];
__device__ __nv_bfloat16 g_yhi[(size_t)Mtot * Dd];
__device__ __nv_bfloat16 g_ylo[(size_t)Mtot * Dd];
__device__ __nv_bfloat16 g_wkhi[(size_t)Dd * Dd];
__device__ __nv_bfloat16 g_wklo[(size_t)Dd * Dd];
__device__ __nv_bfloat16 g_wqhi[(size_t)Dd * Dd];
__device__ __nv_bfloat16 g_wqlo[(size_t)Dd * Dd];
__device__ __nv_bfloat16 g_mthi[(size_t)Dd * Dd];
__device__ __nv_bfloat16 g_mtlo[(size_t)Dd * Dd];
__device__ float g_mtp[(size_t)MTKS * Dd * Dd];
__device__ float g_w[Mtot];
__device__ float g_bt[Mtot];
__device__ float g_u[Dd];
__device__ float g_h[Dd];
__device__ float g_c;
__device__ float g_pm[(size_t)Mtot * NSPLIT];
__device__ float g_pl[(size_t)Mtot * NSPLIT];
__device__ float g_pa[(size_t)Mtot * NSPLIT];
__device__ int   g_qhead;
__device__ int   g_ready[128];        // per 128-row block: #y-tiles done (target 4)

// ---------------------------------------------------------------------------
// reset (graph-replay safe init of queue + flags)
// ---------------------------------------------------------------------------
__global__ void reset_flags()
{
    int tid = threadIdx.x;
    if (tid < 128) g_ready[tid] = 0;
    if (tid == 0) g_qhead = 0;
}

// ---------------------------------------------------------------------------
// split2: fp32 -> bf16 hi/lo (Wk, Wq)
// ---------------------------------------------------------------------------
__global__ void split2(const float* __restrict__ in,
                       __nv_bfloat16* __restrict__ hi,
                       __nv_bfloat16* __restrict__ lo)
{
    size_t i0 = ((size_t)blockIdx.x * 256 + threadIdx.x) * 8;
    float4 a = *(const float4*)(in + i0);
    float4 b = *(const float4*)(in + i0 + 4);
    float v[8] = {a.x, a.y, a.z, a.w, b.x, b.y, b.z, b.w};
    alignas(16) __nv_bfloat16 h[8], l[8];
#pragma unroll
    for (int j = 0; j < 8; ++j) {
        __nv_bfloat16 hh = __float2bfloat16(v[j]);
        h[j] = hh;
        l[j] = __float2bfloat16(v[j] - __bfloat162float(hh));
    }
    *(uint4*)(hi + i0) = *(uint4*)h;
    *(uint4*)(lo + i0) = *(uint4*)l;
}

// ---------------------------------------------------------------------------
// prep kernels
// ---------------------------------------------------------------------------
__global__ void prep_c(const float* __restrict__ bv, const float* __restrict__ Wo)
{
    __shared__ float red[8];
    int tid = threadIdx.x;
    float4 a = ((const float4*)bv)[tid];
    float4 b = ((const float4*)Wo)[tid];
    float s = a.x * b.x + a.y * b.y + a.z * b.z + a.w * b.w;
    #pragma unroll
    for (int off = 16; off; off >>= 1) s += __shfl_xor_sync(0xffffffffu, s, off);
    if ((tid & 31) == 0) red[tid >> 5] = s;
    __syncthreads();
    if (tid < 8) {
        s = red[tid];
        #pragma unroll
        for (int off = 4; off; off >>= 1) s += __shfl_xor_sync(0xffu, s, off);
        if (tid == 0) g_c = s;
    }
}

__global__ void gemv_row(const float* __restrict__ A, const float* __restrict__ vec,
                         float* __restrict__ outv)
{
    __shared__ float red[8];
    int m = blockIdx.x;
    int tid = threadIdx.x;
    float4 a = ((const float4*)(A + (size_t)m * Dd))[tid];
    float4 u = ((const float4*)vec)[tid];
    float s = a.x * u.x + a.y * u.y + a.z * u.z + a.w * u.w;
    #pragma unroll
    for (int off = 16; off; off >>= 1) s += __shfl_xor_sync(0xffffffffu, s, off);
    if ((tid & 31) == 0) red[tid >> 5] = s;
    __syncthreads();
    if (tid < 8) {
        s = red[tid];
        #pragma unroll
        for (int off = 4; off; off >>= 1) s += __shfl_xor_sync(0xffu, s, off);
        if (tid == 0) outv[m] = s;
    }
}

__global__ void fused_x(const float* __restrict__ x,
                        __nv_bfloat16* __restrict__ xhi,
                        __nv_bfloat16* __restrict__ xlo)
{
    __shared__ float red1[8], red2[8];
    int m = blockIdx.x;
    int tid = threadIdx.x;
    float4 a = ((const float4*)(x + (size_t)m * Dd))[tid];
    {
        float v[4] = {a.x, a.y, a.z, a.w};
        alignas(8) __nv_bfloat16 h[4], l[4];
#pragma unroll
        for (int j = 0; j < 4; ++j) {
            __nv_bfloat16 hh = __float2bfloat16(v[j]);
            h[j] = hh;
            l[j] = __float2bfloat16(v[j] - __bfloat162float(hh));
        }
        size_t o = (size_t)m * Dd + tid * 4;
        *(uint2*)(xhi + o) = *(uint2*)h;
        *(uint2*)(xlo + o) = *(uint2*)l;
    }
    float4 u = ((const float4*)g_u)[tid];
    float4 hv = ((const float4*)g_h)[tid];
    float s1 = a.x * u.x + a.y * u.y + a.z * u.z + a.w * u.w;
    float s2 = a.x * hv.x + a.y * hv.y + a.z * hv.z + a.w * hv.w;
    #pragma unroll
    for (int off = 16; off; off >>= 1) {
        s1 += __shfl_xor_sync(0xffffffffu, s1, off);
        s2 += __shfl_xor_sync(0xffffffffu, s2, off);
    }
    if ((tid & 31) == 0) { red1[tid >> 5] = s1; red2[tid >> 5] = s2; }
    __syncthreads();
    if (tid < 8) {
        s1 = red1[tid]; s2 = red2[tid];
        #pragma unroll
        for (int off = 4; off; off >>= 1) {
            s1 += __shfl_xor_sync(0xffu, s1, off);
            s2 += __shfl_xor_sync(0xffu, s2, off);
        }
        if (tid == 0) { g_w[m] = s1 + g_c; g_bt[m] = s2; }
    }
}

// ---------------------------------------------------------------------------
// wmma machinery (validated): CTA tile 128x256, 8 warps of 64x64, k-chunk 32.
// ---------------------------------------------------------------------------
#define TP_E 40
#define A_T_B (128 * 80)
#define B_T_B (256 * 80)
#define OFF_AL A_T_B
#define OFF_BH (2 * A_T_B)
#define OFF_BL (2 * A_T_B + B_T_B)
#define BUF_B  (2 * A_T_B + 2 * B_T_B)
#define STG_P  260
#define STG_B  (128 * STG_P * 4)
#define FL_WS  STG_B
#define FL_BT  (STG_B + 1024)
#define ABT_SMEM   STG_B
#define FLASH_SMEM (STG_B + 2048)

typedef wmma::fragment<wmma::matrix_a, 16, 16, 16, __nv_bfloat16, wmma::row_major> FragA;
typedef wmma::fragment<wmma::matrix_b, 16, 16, 16, __nv_bfloat16, wmma::col_major> FragB;
typedef wmma::fragment<wmma::accumulator, 16, 16, 16, float> FragC;

struct Pref { uint4 r[12]; };

__device__ __forceinline__ void ldg_chunk(Pref& p,
    const __nv_bfloat16* sAh, const __nv_bfloat16* sAl,
    const __nv_bfloat16* sB0h, const __nv_bfloat16* sB0l,
    const __nv_bfloat16* sB1h, const __nv_bfloat16* sB1l, int col)
{
    p.r[0]  = ((const uint4*)(sAh  + col))[0]; p.r[1]  = ((const uint4*)(sAh  + col))[1];
    p.r[2]  = ((const uint4*)(sAl  + col))[0]; p.r[3]  = ((const uint4*)(sAl  + col))[1];
    p.r[4]  = ((const uint4*)(sB0h + col))[0]; p.r[5]  = ((const uint4*)(sB0h + col))[1];
    p.r[6]  = ((const uint4*)(sB0l + col))[0]; p.r[7]  = ((const uint4*)(sB0l + col))[1];
    p.r[8]  = ((const uint4*)(sB1h + col))[0]; p.r[9]  = ((const uint4*)(sB1h + col))[1];
    p.r[10] = ((const uint4*)(sB1l + col))[0]; p.r[11] = ((const uint4*)(sB1l + col))[1];
}

__device__ __forceinline__ void sts_chunk(char* buf, const Pref& p,
                                          uint32_t soffA, uint32_t soffB0,
                                          uint32_t soffB1)
{
    *(uint4*)(buf + soffA)                 = p.r[0];
    *(uint4*)(buf + soffA + 16)            = p.r[1];
    *(uint4*)(buf + OFF_AL + soffA)        = p.r[2];
    *(uint4*)(buf + OFF_AL + soffA + 16)   = p.r[3];
    *(uint4*)(buf + OFF_BH + soffB0)       = p.r[4];
    *(uint4*)(buf + OFF_BH + soffB0 + 16)  = p.r[5];
    *(uint4*)(buf + OFF_BL + soffB0)       = p.r[6];
    *(uint4*)(buf + OFF_BL + soffB0 + 16)  = p.r[7];
    *(uint4*)(buf + OFF_BH + soffB1)       = p.r[8];
    *(uint4*)(buf + OFF_BH + soffB1 + 16)  = p.r[9];
    *(uint4*)(buf + OFF_BL + soffB1)       = p.r[10];
    *(uint4*)(buf + OFF_BL + soffB1 + 16)  = p.r[11];
}

__device__ __forceinline__ void mma_chunk64(const char* buf, int wm, int wn,
                                            FragC (&acc)[4][4])
{
    const __nv_bfloat16* tA  = (const __nv_bfloat16*)(buf);
    const __nv_bfloat16* tAl = (const __nv_bfloat16*)(buf + OFF_AL);
    const __nv_bfloat16* tB  = (const __nv_bfloat16*)(buf + OFF_BH);
    const __nv_bfloat16* tBl = (const __nv_bfloat16*)(buf + OFF_BL);
#pragma unroll
    for (int ks = 0; ks < 2; ++ks) {
        FragA ah[4], al[4];
#pragma unroll
        for (int mi = 0; mi < 4; ++mi) {
            int ro = (64 * wm + 16 * mi) * TP_E + ks * 16;
            wmma::load_matrix_sync(ah[mi], tA + ro, TP_E);
            wmma::load_matrix_sync(al[mi], tAl + ro, TP_E);
        }
#pragma unroll
        for (int pj = 0; pj < 4; ++pj) {
            int ro = (64 * wn + 16 * pj) * TP_E + ks * 16;
            FragB bh, bl;
            wmma::load_matrix_sync(bh, tB + ro, TP_E);
            wmma::load_matrix_sync(bl, tBl + ro, TP_E);
#pragma unroll
            for (int mi = 0; mi < 4; ++mi) {
                wmma::mma_sync(acc[mi][pj], ah[mi], bh, acc[mi][pj]);
                wmma::mma_sync(acc[mi][pj], ah[mi], bl, acc[mi][pj]);
                wmma::mma_sync(acc[mi][pj], al[mi], bh, acc[mi][pj]);
            }
        }
    }
}

__device__ __forceinline__ void store_stage(float* stage, int wm, int wn,
                                            FragC (&acc)[4][4])
{
#pragma unroll
    for (int mi = 0; mi < 4; ++mi)
#pragma unroll
        for (int pj = 0; pj < 4; ++pj)
            wmma::store_matrix_sync(
                stage + (size_t)(64 * wm + 16 * mi) * STG_P + 64 * wn + 16 * pj,
                acc[mi][pj], STG_P, wmma::mem_row_major);
}

// ---------------------------------------------------------------------------
// tile body: bf16 A@B^T, full K, hi/lo bf16 outputs (y tile)
// ---------------------------------------------------------------------------
__device__ void tile_abt(char* sm, int m0, int n0,
                         const __nv_bfloat16* __restrict__ Ahi,
                         const __nv_bfloat16* __restrict__ Alo,
                         const __nv_bfloat16* __restrict__ Bhi,
                         const __nv_bfloat16* __restrict__ Blo,
                         __nv_bfloat16* __restrict__ Chi,
                         __nv_bfloat16* __restrict__ Clo)
{
    int tid = threadIdx.x;
    int wid = tid >> 5;
    int wm = wid & 1, wn = wid >> 1;
    float* stage = (float*)sm;

    int ra_ = tid >> 1;
    int half = tid & 1;
    uint32_t soffA  = (uint32_t)ra_ * 80 + half * 32;
    uint32_t soffB0 = soffA;
    uint32_t soffB1 = soffA + 128u * 80;
    size_t roA  = (size_t)(m0 + ra_) * Dd + half * 16;
    size_t roB0 = (size_t)(n0 + ra_) * Dd + half * 16;
    size_t roB1 = (size_t)(n0 + 128 + ra_) * Dd + half * 16;
    const __nv_bfloat16* sAh  = Ahi + roA;
    const __nv_bfloat16* sAl  = Alo + roA;
    const __nv_bfloat16* sB0h = Bhi + roB0;
    const __nv_bfloat16* sB0l = Blo + roB0;
    const __nv_bfloat16* sB1h = Bhi + roB1;
    const __nv_bfloat16* sB1l = Blo + roB1;

    FragC acc[4][4];
#pragma unroll
    for (int mi = 0; mi < 4; ++mi)
#pragma unroll
        for (int pj = 0; pj < 4; ++pj)
            wmma::fill_fragment(acc[mi][pj], 0.f);

    Pref p;
    ldg_chunk(p, sAh, sAl, sB0h, sB0l, sB1h, sB1l, 0);
    sts_chunk(sm, p, soffA, soffB0, soffB1);
    __syncthreads();

    const int NK = Dd / 32;
    for (int kc = 0; kc < NK; ++kc) {
        char* buf = sm + (size_t)(kc & 1) * BUF_B;
        bool pre = (kc + 1 < NK);
        if (pre) ldg_chunk(p, sAh, sAl, sB0h, sB0l, sB1h, sB1l, (kc + 1) * 32);
        mma_chunk64(buf, wm, wn, acc);
        if (pre) sts_chunk(sm + (size_t)((kc + 1) & 1) * BUF_B, p,
                           soffA, soffB0, soffB1);
        __syncthreads();
    }

    store_stage(stage, wm, wn, acc);
    __syncthreads();

    int r = tid >> 1;
    int c0 = half * 128;
    const float* sr = stage + (size_t)r * STG_P + c0;
    size_t ob = (size_t)(m0 + r) * Dd + n0 + c0;
#pragma unroll
    for (int j = 0; j < 16; ++j) {
        float4 a = ((const float4*)sr)[2 * j];
        float4 b = ((const float4*)sr)[2 * j + 1];
        float v[8] = {a.x, a.y, a.z, a.w, b.x, b.y, b.z, b.w};
        alignas(16) __nv_bfloat16 h[8], l[8];
#pragma unroll
        for (int q = 0; q < 8; ++q) {
            __nv_bfloat16 hh = __float2bfloat16(v[q]);
            h[q] = hh;
            l[q] = __float2bfloat16(v[q] - __bfloat162float(hh));
        }
        *(uint4*)(Chi + ob + j * 8) = *(uint4*)h;
        *(uint4*)(Clo + ob + j * 8) = *(uint4*)l;
    }
}

// ---------------------------------------------------------------------------
// tile body: flash partial (validated R13)
// ---------------------------------------------------------------------------
__device__ void tile_flash(char* sm, int b, int q0, int split)
{
    int tid = threadIdx.x;
    int wid = tid >> 5;
    int wm = wid & 1, wn = wid >> 1;
    int t0 = split * 256;

    float* stage = (float*)sm;
    float* ws  = (float*)(sm + FL_WS);
    float* bts = (float*)(sm + FL_BT);

    int ra_ = tid >> 1;
    int half = tid & 1;
    uint32_t soffA  = (uint32_t)ra_ * 80 + half * 32;
    uint32_t soffB1 = soffA + 128u * 80;
    size_t roA  = ((size_t)b * Ss + q0 + ra_) * Dd + half * 16;
    size_t roB0 = ((size_t)b * Ss + t0 + ra_) * Dd + half * 16;
    size_t roB1 = ((size_t)b * Ss + t0 + 128 + ra_) * Dd + half * 16;
    const __nv_bfloat16* sAh  = g_yhi + roA;
    const __nv_bfloat16* sAl  = g_ylo + roA;
    const __nv_bfloat16* sB0h = g_xhi + roB0;
    const __nv_bfloat16* sB0l = g_xlo + roB0;
    const __nv_bfloat16* sB1h = g_xhi + roB1;
    const __nv_bfloat16* sB1l = g_xlo + roB1;

    ws[tid]  = g_w[(size_t)b * Ss + t0 + tid];
    bts[tid] = g_bt[(size_t)b * Ss + t0 + tid];

    FragC acc[4][4];
#pragma unroll
    for (int mi = 0; mi < 4; ++mi)
#pragma unroll
        for (int pj = 0; pj < 4; ++pj)
            wmma::fill_fragment(acc[mi][pj], 0.f);

    Pref p;
    ldg_chunk(p, sAh, sAl, sB0h, sB0l, sB1h, sB1l, 0);
    sts_chunk(sm, p, soffA, soffA, soffB1);
    __syncthreads();

    const int NK = Dd / 32;
    for (int kc = 0; kc < NK; ++kc) {
        char* buf = sm + (size_t)(kc & 1) * BUF_B;
        bool pre = (kc + 1 < NK);
        if (pre) ldg_chunk(p, sAh, sAl, sB0h, sB0l, sB1h, sB1l, (kc + 1) * 32);
        mma_chunk64(buf, wm, wn, acc);
        if (pre) sts_chunk(sm + (size_t)((kc + 1) & 1) * BUF_B, p,
                           soffA, soffA, soffB1);
        __syncthreads();
    }

    store_stage(stage, wm, wn, acc);
    __syncthreads();

    {
        int row = tid >> 1;
        const float4* rp = (const float4*)(stage + (size_t)row * STG_P + half * 128);
        const float4* btp = (const float4*)(bts + half * 128);
        float m = -1e30f;
#pragma unroll 8
        for (int j = 0; j < 32; ++j) {
            float4 s4 = rp[j];
            float4 b4 = btp[j];
            s4.x += b4.x; s4.y += b4.y; s4.z += b4.z; s4.w += b4.w;
            m = fmaxf(m, fmaxf(fmaxf(s4.x, s4.y), fmaxf(s4.z, s4.w)));
        }
        m = fmaxf(m, __shfl_xor_sync(0xffffffffu, m, 1));
        float tl = 0.f, ta = 0.f;
        const float4* wp = (const float4*)(ws + half * 128);
#pragma unroll 8
        for (int j = 0; j < 32; ++j) {
            float4 s4 = rp[j];
            float4 b4 = btp[j];
            float4 w4 = wp[j];
            float p0 = __expf(s4.x + b4.x - m);
            float p1 = __expf(s4.y + b4.y - m);
            float p2 = __expf(s4.z + b4.z - m);
            float p3 = __expf(s4.w + b4.w - m);
            tl += (p0 + p1) + (p2 + p3);
            ta += p0 * w4.x + p1 * w4.y + p2 * w4.z + p3 * w4.w;
        }
        tl += __shfl_xor_sync(0xffffffffu, tl, 1);
        ta += __shfl_xor_sync(0xffffffffu, ta, 1);
        if (half == 0) {
            size_t idx = ((size_t)b * Ss + q0 + row) * NSPLIT + split;
            g_pm[idx] = m;
            g_pl[idx] = tl;
            g_pa[idx] = ta;
        }
    }
}

// ---------------------------------------------------------------------------
// persistent kernel: atomic work queue over 512 y tiles then 1024 flash tiles.
// Flash tiles wait on per-rowblock ready counters (4 y tiles each).
// ---------------------------------------------------------------------------
__global__ void __launch_bounds__(256, 1)
persistent_k()
{
    extern __shared__ char sm[];
    __shared__ int s_t;

    for (;;) {
        if (threadIdx.x == 0) s_t = atomicAdd(&g_qhead, 1);
        __syncthreads();
        int t = s_t;
        __syncthreads();
        if (t >= NT_ALL) return;

        if (t < NT_Y) {
            int rb = t >> 2;               // rowblock 0..127
            int nb = t & 3;
            tile_abt(sm, rb * 128, nb * 256,
                     g_xhi, g_xlo, g_mthi, g_mtlo, g_yhi, g_ylo);
            __threadfence();
            __syncthreads();
            if (threadIdx.x == 0) atomicAdd(&g_ready[rb], 1);
        } else {
            int f = t - NT_Y;
            int rb = f >> 3;               // rowblock 0..127
            int split = f & 7;
            if (threadIdx.x == 0) {
                while (atomicAdd(&g_ready[rb], 0) < 4) {}
                __threadfence();
            }
            __syncthreads();
            tile_flash(sm, rb >> 4, (rb & 15) * 128, split);
            __syncthreads();
        }
    }
}

// ---------------------------------------------------------------------------
// Mt k-split GEMM + reduce (validated R13)
// ---------------------------------------------------------------------------
__global__ void __launch_bounds__(256, 1)
wmma_abt_ks(const __nv_bfloat16* __restrict__ Ahi, const __nv_bfloat16* __restrict__ Alo,
            const __nv_bfloat16* __restrict__ Bhi, const __nv_bfloat16* __restrict__ Blo,
            float* __restrict__ Cpart)
{
    extern __shared__ char sm[];
    int tid = threadIdx.x;
    int wid = tid >> 5;
    int wm = wid & 1, wn = wid >> 1;
    int m0 = blockIdx.y * 128;
    int n0 = blockIdx.x * 256;
    int k0 = blockIdx.z * (Dd / MTKS);
    float* C = Cpart + (size_t)blockIdx.z * Dd * Dd;

    float* stage = (float*)sm;

    int ra_ = tid >> 1;
    int half = tid & 1;
    uint32_t soffA  = (uint32_t)ra_ * 80 + half * 32;
    uint32_t soffB0 = soffA;
    uint32_t soffB1 = soffA + 128u * 80;
    size_t roA  = (size_t)(m0 + ra_) * Dd + half * 16 + k0;
    size_t roB0 = (size_t)(n0 + ra_) * Dd + half * 16 + k0;
    size_t roB1 = (size_t)(n0 + 128 + ra_) * Dd + half * 16 + k0;
    const __nv_bfloat16* sAh  = Ahi + roA;
    const __nv_bfloat16* sAl  = Alo + roA;
    const __nv_bfloat16* sB0h = Bhi + roB0;
    const __nv_bfloat16* sB0l = Blo + roB0;
    const __nv_bfloat16* sB1h = Bhi + roB1;
    const __nv_bfloat16* sB1l = Blo + roB1;

    FragC acc[4][4];
#pragma unroll
    for (int mi = 0; mi < 4; ++mi)
#pragma unroll
        for (int pj = 0; pj < 4; ++pj)
            wmma::fill_fragment(acc[mi][pj], 0.f);

    Pref p;
    ldg_chunk(p, sAh, sAl, sB0h, sB0l, sB1h, sB1l, 0);
    sts_chunk(sm, p, soffA, soffB0, soffB1);
    __syncthreads();

    const int NK = (Dd / MTKS) / 32;
    for (int kc = 0; kc < NK; ++kc) {
        char* buf = sm + (size_t)(kc & 1) * BUF_B;
        bool pre = (kc + 1 < NK);
        if (pre) ldg_chunk(p, sAh, sAl, sB0h, sB0l, sB1h, sB1l, (kc + 1) * 32);
        mma_chunk64(buf, wm, wn, acc);
        if (pre) sts_chunk(sm + (size_t)((kc + 1) & 1) * BUF_B, p,
                           soffA, soffB0, soffB1);
        __syncthreads();
    }

    store_stage(stage, wm, wn, acc);
    __syncthreads();

    int r = tid >> 1;
    int c0 = half * 128;
    const float* sr = stage + (size_t)r * STG_P + c0;
    float* cr = C + (size_t)(m0 + r) * Dd + n0 + c0;
#pragma unroll
    for (int j = 0; j < 32; ++j)
        ((float4*)cr)[j] = ((const float4*)sr)[j];
}

__global__ void mt_reduce(__nv_bfloat16* __restrict__ hi,
                          __nv_bfloat16* __restrict__ lo)
{
    size_t i0 = ((size_t)blockIdx.x * 256 + threadIdx.x) * 4;
    float4 s = *(const float4*)(g_mtp + i0);
#pragma unroll
    for (int z = 1; z < MTKS; ++z) {
        float4 t = *(const float4*)(g_mtp + (size_t)z * Dd * Dd + i0);
        s.x += t.x; s.y += t.y; s.z += t.z; s.w += t.w;
    }
    float v[4] = {s.x, s.y, s.z, s.w};
    alignas(8) __nv_bfloat16 h[4], l[4];
#pragma unroll
    for (int j = 0; j < 4; ++j) {
        __nv_bfloat16 hh = __float2bfloat16(v[j]);
        h[j] = hh;
        l[j] = __float2bfloat16(v[j] - __bfloat162float(hh));
    }
    *(uint2*)(hi + i0) = *(uint2*)h;
    *(uint2*)(lo + i0) = *(uint2*)l;
}

// ---------------------------------------------------------------------------
// combine partials
// ---------------------------------------------------------------------------
__global__ void combine_partials(const float* __restrict__ bo,
                                 float* __restrict__ out)
{
    int r = blockIdx.x * 256 + threadIdx.x;
    const float* pm = g_pm + (size_t)r * NSPLIT;
    const float* pl = g_pl + (size_t)r * NSPLIT;
    const float* pa = g_pa + (size_t)r * NSPLIT;
    float M = -1e30f;
#pragma unroll
    for (int i = 0; i < NSPLIT; ++i) M = fmaxf(M, pm[i]);
    float L = 0.f, A = 0.f;
#pragma unroll
    for (int i = 0; i < NSPLIT; ++i) {
        float f = __expf(pm[i] - M);
        L += pl[i] * f;
        A += pa[i] * f;
    }
    out[r] = A / L + bo[0];
}

// ---------------------------------------------------------------------------
extern "C" void kernel_launch(void* const* d_in, const int* in_sizes, int n_in,
                              void* d_out, int out_size)
{
    const float* x  = (const float*)d_in[0];
    const float* Wq = (const float*)d_in[1];
    const float* bq = (const float*)d_in[2];
    const float* Wk = (const float*)d_in[3];
    const float* bk = (const float*)d_in[4];
    const float* Wv = (const float*)d_in[5];
    const float* bv = (const float*)d_in[6];
    const float* Wo = (const float*)d_in[7];
    const float* bo = (const float*)d_in[8];
    float* out = (float*)d_out;
    (void)bk; (void)in_sizes; (void)n_in; (void)out_size;

    static int nsm = 0;
    if (!nsm) {
        cudaDeviceGetAttribute(&nsm, cudaDevAttrMultiProcessorCount, 0);
        cudaFuncSetAttribute(wmma_abt_ks,
                             cudaFuncAttributeMaxDynamicSharedMemorySize, ABT_SMEM);
        cudaFuncSetAttribute(persistent_k,
                             cudaFuncAttributeMaxDynamicSharedMemorySize, FLASH_SMEM);
    }

    __nv_bfloat16 *xhi, *xlo, *wkhi, *wklo, *wqhi, *wqlo, *mthi, *mtlo;
    cudaGetSymbolAddress((void**)&xhi, g_xhi);
    cudaGetSymbolAddress((void**)&xlo, g_xlo);
    cudaGetSymbolAddress((void**)&wkhi, g_wkhi);
    cudaGetSymbolAddress((void**)&wklo, g_wklo);
    cudaGetSymbolAddress((void**)&wqhi, g_wqhi);
    cudaGetSymbolAddress((void**)&wqlo, g_wqlo);
    cudaGetSymbolAddress((void**)&mthi, g_mthi);
    cudaGetSymbolAddress((void**)&mtlo, g_mtlo);
    float *uu, *hh, *mtp;
    cudaGetSymbolAddress((void**)&uu, g_u);
    cudaGetSymbolAddress((void**)&hh, g_h);
    cudaGetSymbolAddress((void**)&mtp, g_mtp);

    // reset queue + ready flags (graph-replay safe)
    reset_flags<<<1, 128>>>();

    // weight splits
    split2<<<(size_t)Dd * Dd / 2048, 256>>>(Wk, wkhi, wklo);
    split2<<<(size_t)Dd * Dd / 2048, 256>>>(Wq, wqhi, wqlo);

    // scalars + vectors + fused x split / w / bt
    prep_c<<<1, 256>>>(bv, Wo);
    gemv_row<<<Dd, 256>>>(Wv, Wo, uu);
    gemv_row<<<Dd, 256>>>(Wk, bq, hh);
    fused_x<<<Mtot, 256>>>(x, xhi, xlo);

    // Mt = Wk @ Wq^T (k-split + reduce)
    {
        dim3 gm(Dd / 256, Dd / 128, MTKS);
        wmma_abt_ks<<<gm, 256, ABT_SMEM>>>(wkhi, wklo, wqhi, wqlo, mtp);
        mt_reduce<<<(size_t)Dd * Dd / 1024, 256>>>(mthi, mtlo);
    }

    // fused persistent y-GEMM + flash (work queue, flag-synced)
    persistent_k<<<nsm, 256, FLASH_SMEM>>>();

    combine_partials<<<Mtot / 256, 256>>>(bo, out);
}